// round 2
// baseline (speedup 1.0000x reference)
#include <cuda_runtime.h>
#include <cuda_bf16.h>

// ---------------------------------------------------------------------------
// Encoder_59425167507712: 4-layer transformer encoder, fp32.
// B=8, S=512, D=1024, DK=64 (head-0 only per source bug), FF=4096, L=4.
// Strategy (round 0): fp32 SMEM-tiled GEMM (128x128x8, 8x8 micro) with fused
// epilogues (bias / bias+relu / residual+BN), batched GEMMs for attention.
// ---------------------------------------------------------------------------

#define Bq   8
#define Sq   512
#define Dm   1024
#define DKh  64
#define FFd  4096
#define NL   4
#define Mrows (Bq*Sq)   // 4096

// Scratch (device globals: no allocation allowed)
__device__ float g_x [(long)Mrows*Dm];     // 16 MB activations
__device__ float g_q [(long)Mrows*DKh];
__device__ float g_k [(long)Mrows*DKh];
__device__ float g_v [(long)Mrows*DKh];
__device__ float g_hd[(long)Mrows*DKh];
__device__ float g_sc[(long)Bq*Sq*Sq];     // 8 MB scores
__device__ float g_h [(long)Mrows*FFd];    // 64 MB FFN hidden

constexpr int BM = 128, BN = 128, BKt = 8, TM = 8, TN = 8;

enum { EPI_NONE = 0, EPI_BIAS = 1, EPI_BIAS_RELU = 2, EPI_RESID_BN = 3 };

// C[z] = epilogue( alpha * A[z] @ (TRANSB ? B[z]^T : B[z]) )
// A: [M,K] row-major. B: TRANSB ? [N,K] : [K,N] row-major.
// Requires M % 128 == 0, K % 8 == 0, N % 4 == 0 (all true for this model).
template <int EPI, bool TRANSB>
__global__ void __launch_bounds__(256, 2)
gemm_k(const float* __restrict__ A, const float* __restrict__ B,
       const float* __restrict__ bias, float* __restrict__ C,
       int M, int N, int K,
       long sA, long sB, long sC, float alpha,
       const float* __restrict__ resid,
       const float* __restrict__ gamma, const float* __restrict__ beta,
       const float* __restrict__ mean,  const float* __restrict__ var)
{
    __shared__ float As[BKt][BM + 4];
    __shared__ float Bs[BKt][BN + 4];

    A += (long)blockIdx.z * sA;
    B += (long)blockIdx.z * sB;
    C += (long)blockIdx.z * sC;

    const int m0 = blockIdx.y * BM;
    const int n0 = blockIdx.x * BN;
    const int tid = threadIdx.x;
    const int tx = tid & 15;        // 16 columns of threads
    const int ty = tid >> 4;        // 16 rows of threads

    // A tile load: 128 rows x 8 cols, float4 along K
    const int arow = tid >> 1;
    const int acol = (tid & 1) << 2;
    // B tile load (no trans): 8 rows x 128 cols, float4 along N
    const int brow = tid >> 5;
    const int bcol = (tid & 31) << 2;
    // B tile load (trans): row n = tid/2, float4 along K
    const int bn  = tid >> 1;
    const int bkk = (tid & 1) << 2;

    float acc[TM][TN];
#pragma unroll
    for (int i = 0; i < TM; i++)
#pragma unroll
        for (int j = 0; j < TN; j++) acc[i][j] = 0.f;

    for (int k0 = 0; k0 < K; k0 += BKt) {
        float4 av = *reinterpret_cast<const float4*>(
            A + (long)(m0 + arow) * K + k0 + acol);
        As[acol + 0][arow] = av.x;
        As[acol + 1][arow] = av.y;
        As[acol + 2][arow] = av.z;
        As[acol + 3][arow] = av.w;

        if (!TRANSB) {
            float4 bv = make_float4(0.f, 0.f, 0.f, 0.f);
            if (n0 + bcol < N)
                bv = *reinterpret_cast<const float4*>(
                    B + (long)(k0 + brow) * N + n0 + bcol);
            Bs[brow][bcol + 0] = bv.x;
            Bs[brow][bcol + 1] = bv.y;
            Bs[brow][bcol + 2] = bv.z;
            Bs[brow][bcol + 3] = bv.w;
        } else {
            float4 bv = make_float4(0.f, 0.f, 0.f, 0.f);
            if (n0 + bn < N)
                bv = *reinterpret_cast<const float4*>(
                    B + (long)(n0 + bn) * K + k0 + bkk);
            Bs[bkk + 0][bn] = bv.x;
            Bs[bkk + 1][bn] = bv.y;
            Bs[bkk + 2][bn] = bv.z;
            Bs[bkk + 3][bn] = bv.w;
        }
        __syncthreads();

#pragma unroll
        for (int kk = 0; kk < BKt; kk++) {
            float4 a0 = *reinterpret_cast<const float4*>(&As[kk][ty * TM]);
            float4 a1 = *reinterpret_cast<const float4*>(&As[kk][ty * TM + 4]);
            float4 b0 = *reinterpret_cast<const float4*>(&Bs[kk][tx * TN]);
            float4 b1 = *reinterpret_cast<const float4*>(&Bs[kk][tx * TN + 4]);
            float a[TM] = {a0.x, a0.y, a0.z, a0.w, a1.x, a1.y, a1.z, a1.w};
            float b[TN] = {b0.x, b0.y, b0.z, b0.w, b1.x, b1.y, b1.z, b1.w};
#pragma unroll
            for (int i = 0; i < TM; i++)
#pragma unroll
                for (int j = 0; j < TN; j++)
                    acc[i][j] = fmaf(a[i], b[j], acc[i][j]);
        }
        __syncthreads();
    }

#pragma unroll
    for (int i = 0; i < TM; i++) {
        const int m = m0 + ty * TM + i;
#pragma unroll
        for (int j = 0; j < TN; j++) {
            const int n = n0 + tx * TN + j;
            if (n < N) {
                float v = acc[i][j] * alpha;
                if (EPI == EPI_BIAS || EPI == EPI_BIAS_RELU || EPI == EPI_RESID_BN)
                    v += bias[n];
                if (EPI == EPI_BIAS_RELU)
                    v = fmaxf(v, 0.f);
                if (EPI == EPI_RESID_BN) {
                    v += resid[(long)m * N + n];
                    v = gamma[n] * (v - mean[n]) * rsqrtf(var[n] + 1e-3f) + beta[n];
                }
                C[(long)m * N + n] = v;
            }
        }
    }
}

// x[b*S+s, d] = emb[seq[b*S+s], d] + pes[s, 0]
__global__ void embed_k(const int* __restrict__ seq,
                        const float* __restrict__ emb,
                        const float* __restrict__ pes,
                        float* __restrict__ x)
{
    long idx = (long)blockIdx.x * blockDim.x + threadIdx.x;
    int d = (int)(idx & (Dm - 1));
    long bs = idx >> 10;
    int s = (int)(bs & (Sq - 1));
    x[idx] = emb[(long)seq[bs] * Dm + d] + pes[(long)s * Dm];
}

// Row softmax over 512 columns; one block (256 threads) per row.
__global__ void softmax_k(float* __restrict__ S)
{
    float* p = S + (long)blockIdx.x * Sq;
    const int t = threadIdx.x;
    __shared__ float red[256];

    float v0 = p[t], v1 = p[t + 256];
    red[t] = fmaxf(v0, v1);
    __syncthreads();
    for (int o = 128; o > 0; o >>= 1) {
        if (t < o) red[t] = fmaxf(red[t], red[t + o]);
        __syncthreads();
    }
    const float m = red[0];
    __syncthreads();

    float e0 = __expf(v0 - m), e1 = __expf(v1 - m);
    red[t] = e0 + e1;
    __syncthreads();
    for (int o = 128; o > 0; o >>= 1) {
        if (t < o) red[t] += red[t + o];
        __syncthreads();
    }
    const float inv = 1.f / red[0];
    p[t]       = e0 * inv;
    p[t + 256] = e1 * inv;
}

template <int EPI, bool TB>
static inline void gemm(const float* A, const float* B, const float* bias,
                        float* C, int M, int N, int K, int batch,
                        long sA, long sB, long sC, float alpha,
                        const float* resid = nullptr,
                        const float* gamma = nullptr, const float* beta = nullptr,
                        const float* mean = nullptr,  const float* var = nullptr)
{
    dim3 grid((N + BN - 1) / BN, M / BM, batch);
    gemm_k<EPI, TB><<<grid, 256>>>(A, B, bias, C, M, N, K, sA, sB, sC, alpha,
                                   resid, gamma, beta, mean, var);
}

extern "C" void kernel_launch(void* const* d_in, const int* in_sizes, int n_in,
                              void* d_out, int out_size)
{
    const int*   seq = (const int*)  d_in[0];
    const float* emb = (const float*)d_in[1];
    const float* pes = (const float*)d_in[2];
    const float* wq  = (const float*)d_in[3];
    const float* bq  = (const float*)d_in[4];
    const float* wk  = (const float*)d_in[5];
    const float* bk  = (const float*)d_in[6];
    const float* wv  = (const float*)d_in[7];
    const float* bv  = (const float*)d_in[8];
    const float* wo  = (const float*)d_in[9];
    const float* bo  = (const float*)d_in[10];
    const float* ag  = (const float*)d_in[11];
    const float* ab  = (const float*)d_in[12];
    const float* am  = (const float*)d_in[13];
    const float* avv = (const float*)d_in[14];
    const float* w1  = (const float*)d_in[15];
    const float* b1  = (const float*)d_in[16];
    const float* w2  = (const float*)d_in[17];
    const float* b2  = (const float*)d_in[18];
    const float* fg  = (const float*)d_in[19];
    const float* fb  = (const float*)d_in[20];
    const float* fm  = (const float*)d_in[21];
    const float* fv  = (const float*)d_in[22];
    float* out = (float*)d_out;

    float *px, *pq, *pk, *pv, *phd, *psc, *ph;
    cudaGetSymbolAddress((void**)&px,  g_x);
    cudaGetSymbolAddress((void**)&pq,  g_q);
    cudaGetSymbolAddress((void**)&pk,  g_k);
    cudaGetSymbolAddress((void**)&pv,  g_v);
    cudaGetSymbolAddress((void**)&phd, g_hd);
    cudaGetSymbolAddress((void**)&psc, g_sc);
    cudaGetSymbolAddress((void**)&ph,  g_h);

    embed_k<<<(Mrows * Dm) / 256, 256>>>(seq, emb, pes, px);

    for (int l = 0; l < NL; l++) {
        // Q, K, V projections: [4096,1024]@[1024,64] + bias
        gemm<EPI_BIAS, false>(px, wq + (long)l * Dm * DKh, bq + l * DKh, pq,
                              Mrows, DKh, Dm, 1, 0, 0, 0, 1.f);
        gemm<EPI_BIAS, false>(px, wk + (long)l * Dm * DKh, bk + l * DKh, pk,
                              Mrows, DKh, Dm, 1, 0, 0, 0, 1.f);
        gemm<EPI_BIAS, false>(px, wv + (long)l * Dm * DKh, bv + l * DKh, pv,
                              Mrows, DKh, Dm, 1, 0, 0, 0, 1.f);

        // scores = Q @ K^T * 1/sqrt(64), batched over B
        gemm<EPI_NONE, true>(pq, pk, nullptr, psc, Sq, Sq, DKh, Bq,
                             (long)Sq * DKh, (long)Sq * DKh, (long)Sq * Sq,
                             0.125f);

        softmax_k<<<Mrows, 256>>>(psc);

        // head = P @ V, batched over B
        gemm<EPI_NONE, false>(psc, pv, nullptr, phd, Sq, DKh, Sq, Bq,
                              (long)Sq * Sq, (long)Sq * DKh, (long)Sq * DKh,
                              1.f);

        // x = BN(x + head @ wo + bo)
        gemm<EPI_RESID_BN, false>(phd, wo + (long)l * DKh * Dm, bo + l * Dm, px,
                                  Mrows, Dm, DKh, 1, 0, 0, 0, 1.f,
                                  px, ag + l * Dm, ab + l * Dm,
                                  am + l * Dm, avv + l * Dm);

        // h = relu(x @ w1 + b1)
        gemm<EPI_BIAS_RELU, false>(px, w1 + (long)l * Dm * FFd, b1 + l * FFd,
                                   ph, Mrows, FFd, Dm, 1, 0, 0, 0, 1.f);

        // x = BN(x + h @ w2 + b2); final layer writes straight to d_out
        float* dst = (l == NL - 1) ? out : px;
        gemm<EPI_RESID_BN, false>(ph, w2 + (long)l * FFd * Dm, b2 + l * Dm, dst,
                                  Mrows, Dm, FFd, 1, 0, 0, 0, 1.f,
                                  px, fg + l * Dm, fb + l * Dm,
                                  fm + l * Dm, fv + l * Dm);
    }
}

// round 5
// speedup vs baseline: 2.9948x; 2.9948x over previous
#include <cuda_runtime.h>
#include <cuda_bf16.h>
#include <cstdint>

#define Bq 8
#define Sq 512
#define Dm 1024
#define DKh 64
#define FFd 4096
#define NL 4
#define Mrows 4096

// ---------------- scratch ----------------------------------------------------
__device__ float         g_x  [(size_t)Mrows*Dm];
__device__ __nv_bfloat16 g_xh [(size_t)Mrows*Dm];
__device__ __nv_bfloat16 g_xl [(size_t)Mrows*Dm];
__device__ float         g_qkv[(size_t)Mrows*192];
__device__ float         g_sc [(size_t)Bq*Sq*Sq];
__device__ float         g_hd [(size_t)Mrows*DKh];
__device__ __nv_bfloat16 g_hh [(size_t)Mrows*FFd];
__device__ __nv_bfloat16 g_hl [(size_t)Mrows*FFd];
__device__ __nv_bfloat16 g_wqh[(size_t)NL*192*Dm];
__device__ __nv_bfloat16 g_wql[(size_t)NL*192*Dm];
__device__ __nv_bfloat16 g_w1h[(size_t)NL*FFd*Dm];
__device__ __nv_bfloat16 g_w1l[(size_t)NL*FFd*Dm];
__device__ __nv_bfloat16 g_w2h[(size_t)NL*Dm*FFd];
__device__ __nv_bfloat16 g_w2l[(size_t)NL*Dm*FFd];
__device__ float         g_bqkv[NL*192];

// ---------------- helpers -----------------------------------------------------
__device__ __forceinline__ uint32_t smem_u32(const void* p){
    uint32_t a;
    asm("{ .reg .u64 t; cvta.to.shared.u64 t, %1; cvt.u32.u64 %0, t; }":"=r"(a):"l"(p));
    return a;
}
__device__ __forceinline__ void cpa16(uint32_t d, const void* s){
    asm volatile("cp.async.cg.shared.global [%0], [%1], 16;"::"r"(d),"l"(s));
}
__device__ __forceinline__ void cpa_commit(){ asm volatile("cp.async.commit_group;":::"memory"); }
__device__ __forceinline__ void cpa_wait1(){ asm volatile("cp.async.wait_group 1;":::"memory"); }
__device__ __forceinline__ void cpa_wait0(){ asm volatile("cp.async.wait_group 0;":::"memory"); }

#define LDMX4(r, addr) \
    asm volatile("ldmatrix.sync.aligned.m8n8.x4.shared.b16 {%0,%1,%2,%3}, [%4];" \
        : "=r"((r)[0]),"=r"((r)[1]),"=r"((r)[2]),"=r"((r)[3]) : "r"(addr))

#define MMA16816(c, a, b0v, b1v) \
    asm volatile("mma.sync.aligned.m16n8k16.row.col.f32.bf16.bf16.f32 " \
        "{%0,%1,%2,%3}, {%4,%5,%6,%7}, {%8,%9}, {%0,%1,%2,%3};" \
        : "+f"((c)[0]),"+f"((c)[1]),"+f"((c)[2]),"+f"((c)[3]) \
        : "r"((a)[0]),"r"((a)[1]),"r"((a)[2]),"r"((a)[3]), "r"(b0v),"r"(b1v))

// ---------------- split-bf16 HMMA GEMM  C = epi(A @ B^T) -----------------------
// A: [M,K] bf16 hi/lo row-major. B: [N,K] bf16 hi/lo row-major. K%64==0, M%128==0.
#define TCE_BIAS 0
#define TCE_RELU 1
#define TCE_BN   2

template <int BN_, int EPI, bool WB16>
__global__ void __launch_bounds__(256, 1)
mma_gemm(const __nv_bfloat16* __restrict__ Ah, const __nv_bfloat16* __restrict__ Al,
         const __nv_bfloat16* __restrict__ Bh, const __nv_bfloat16* __restrict__ Bl,
         const float* __restrict__ bias, int K,
         float* __restrict__ Cf, int ldc,
         __nv_bfloat16* __restrict__ Oh, __nv_bfloat16* __restrict__ Ol,
         const float* __restrict__ resid,
         const float* __restrict__ gamma, const float* __restrict__ beta,
         const float* __restrict__ mean,  const float* __restrict__ var)
{
    extern __shared__ __align__(1024) char smem[];
    constexpr int STG = 32768 + 2*BN_*128;   // Ah(16K)+Al(16K)+Bh+Bl per stage
    constexpr int WN  = BN_/2;               // warp n-width (warps 4x2)
    constexpr int NP  = WN/16;               // ldmatrix n16 pairs per warp
    constexpr int NT  = WN/8;                // n8 mma tiles per warp

    const uint32_t sb = smem_u32(smem);
    const int tid = threadIdx.x, wid = tid>>5, lane = tid&31;
    const int m0 = blockIdx.y*128, n0 = blockIdx.x*BN_;
    const int wm = (wid>>1)*32,    wn = (wid&1)*WN;

    // ldmatrix addressing: row base (no swizzle on row part), column selector
    // gets XORed per k-step: col = ((sg<<4) | (ks<<5)) ^ ((row&7)<<4).
    const int l15 = lane & 15, sg = lane >> 4;
    const int rA = wm + l15, rB = wn + l15;
    const uint32_t baseA = (uint32_t)rA * 128;
    const uint32_t baseB = (uint32_t)rB * 128;
    const uint32_t xorA  = ((uint32_t)(rA & 7)) << 4;
    const uint32_t xorB  = ((uint32_t)(rB & 7)) << 4;
    const uint32_t sgo   = ((uint32_t)sg) << 4;

    float acc[2][NT][4];
#pragma unroll
    for (int mt=0;mt<2;mt++)
#pragma unroll
        for (int nt=0;nt<NT;nt++)
#pragma unroll
            for (int q=0;q<4;q++) acc[mt][nt][q] = 0.f;

    auto load_chunk = [&](int ck, int s){
        const int ko = ck << 6;
        const uint32_t aAh = sb + s*STG, aAl = aAh + 16384;
        const uint32_t aBh = aAh + 32768, aBl = aBh + BN_*128;
#pragma unroll
        for (int i = 0; i < 4; i++) {                 // A: 128 rows x 8 segs
            int idx = tid + (i<<8); int r = idx>>3, seg = idx&7;
            uint32_t off = (r<<7)+(seg<<4), sw = off ^ ((off>>3)&0x70);
            size_t g = (size_t)(m0+r)*K + ko + (seg<<3);
            cpa16(aAh+sw, Ah+g); cpa16(aAl+sw, Al+g);
        }
#pragma unroll
        for (int i = 0; i < BN_/32; i++) {            // B: BN_ rows x 8 segs
            int idx = tid + (i<<8); int r = idx>>3, seg = idx&7;
            uint32_t off = (r<<7)+(seg<<4), sw = off ^ ((off>>3)&0x70);
            size_t g = (size_t)(n0+r)*K + ko + (seg<<3);
            cpa16(aBh+sw, Bh+g); cpa16(aBl+sw, Bl+g);
        }
    };

    const int NC = K >> 6;
    load_chunk(0, 0);
    cpa_commit();

    for (int c = 0; c < NC; c++) {
        if (c+1 < NC) { load_chunk(c+1, (c+1)&1); cpa_commit(); cpa_wait1(); }
        else          { cpa_wait0(); }
        __syncthreads();

        const uint32_t aAh = sb + (c&1)*STG, aAl = aAh + 16384;
        const uint32_t aBh = aAh + 32768,    aBl = aBh + BN_*128;
#pragma unroll
        for (int ks = 0; ks < 4; ks++) {
            const uint32_t cA = (sgo | ((uint32_t)ks << 5)) ^ xorA;
            const uint32_t cB = (sgo | ((uint32_t)ks << 5)) ^ xorB;
            uint32_t ahf[2][4], alf[2][4], bhf[NP][4], blf[NP][4];
#pragma unroll
            for (int mt=0;mt<2;mt++) {
                LDMX4(ahf[mt], aAh + baseA + mt*2048 + cA);
                LDMX4(alf[mt], aAl + baseA + mt*2048 + cA);
            }
#pragma unroll
            for (int np=0;np<NP;np++) {
                LDMX4(bhf[np], aBh + baseB + np*2048 + cB);
                LDMX4(blf[np], aBl + baseB + np*2048 + cB);
            }
#pragma unroll
            for (int mt=0;mt<2;mt++)
#pragma unroll
                for (int np=0;np<NP;np++) {
                    MMA16816(acc[mt][2*np],   ahf[mt], bhf[np][0], bhf[np][2]);
                    MMA16816(acc[mt][2*np+1], ahf[mt], bhf[np][1], bhf[np][3]);
                    MMA16816(acc[mt][2*np],   ahf[mt], blf[np][0], blf[np][2]);
                    MMA16816(acc[mt][2*np+1], ahf[mt], blf[np][1], blf[np][3]);
                    MMA16816(acc[mt][2*np],   alf[mt], bhf[np][0], bhf[np][2]);
                    MMA16816(acc[mt][2*np+1], alf[mt], bhf[np][1], bhf[np][3]);
                }
        }
        __syncthreads();
    }

    // ---- epilogue ----
    const int rb = m0 + wm + (lane>>2);
    const int cb = n0 + wn + (lane&3)*2;

    auto epi = [&](int row, int col, float v0, float v1){
        v0 += bias[col]; v1 += bias[col+1];
        if (EPI == TCE_RELU) { v0 = fmaxf(v0, 0.f); v1 = fmaxf(v1, 0.f); }
        if (EPI == TCE_BN) {
            float2 rs = *(const float2*)(resid + (size_t)row*ldc + col);
            v0 += rs.x; v1 += rs.y;
            v0 = gamma[col]  *(v0 - mean[col])  *rsqrtf(var[col]  +1e-3f) + beta[col];
            v1 = gamma[col+1]*(v1 - mean[col+1])*rsqrtf(var[col+1]+1e-3f) + beta[col+1];
        }
        if (EPI != TCE_RELU)
            *(float2*)(Cf + (size_t)row*ldc + col) = make_float2(v0, v1);
        if (WB16 || EPI == TCE_RELU) {
            __nv_bfloat16 h0 = __float2bfloat16(v0), h1 = __float2bfloat16(v1);
            *(__nv_bfloat162*)(Oh + (size_t)row*ldc + col) = __halves2bfloat162(h0, h1);
            *(__nv_bfloat162*)(Ol + (size_t)row*ldc + col) = __halves2bfloat162(
                __float2bfloat16(v0 - __bfloat162float(h0)),
                __float2bfloat16(v1 - __bfloat162float(h1)));
        }
    };

#pragma unroll
    for (int mt=0;mt<2;mt++)
#pragma unroll
        for (int nt=0;nt<NT;nt++) {
            const int col = cb + nt*8;
            epi(rb + mt*16,     col, acc[mt][nt][0], acc[mt][nt][1]);
            epi(rb + mt*16 + 8, col, acc[mt][nt][2], acc[mt][nt][3]);
        }
}

// ---------------- weight transpose + bf16 split: in[K,N] -> out[N,K] ----------
__global__ void wsplit(const float* __restrict__ in, int K, int N,
                       __nv_bfloat16* __restrict__ oh, __nv_bfloat16* __restrict__ ol)
{
    __shared__ float t[32][33];
    const int k0 = blockIdx.x*32, n0 = blockIdx.y*32;
    const int tx = threadIdx.x, ty = threadIdx.y;
#pragma unroll
    for (int i = ty; i < 32; i += 8)
        t[i][tx] = in[(size_t)(k0+i)*N + n0 + tx];
    __syncthreads();
#pragma unroll
    for (int i = ty; i < 32; i += 8) {
        float val = t[tx][i];
        __nv_bfloat16 h = __float2bfloat16(val);
        oh[(size_t)(n0+i)*K + k0 + tx] = h;
        ol[(size_t)(n0+i)*K + k0 + tx] = __float2bfloat16(val - __bfloat162float(h));
    }
}

__global__ void biaspack(const float* bq, const float* bk, const float* bv, float* o)
{
    int t = threadIdx.x + blockIdx.x*256;
    if (t >= NL*192) return;
    int l = t/192, j = t%192;
    o[t] = (j < 64) ? bq[l*64+j] : (j < 128) ? bk[l*64+j-64] : bv[l*64+j-128];
}

// ---------------- embed + split ----------------------------------------------
__global__ void embed_k(const int* __restrict__ seq, const float* __restrict__ emb,
                        const float* __restrict__ pes, float* __restrict__ x,
                        __nv_bfloat16* __restrict__ xh, __nv_bfloat16* __restrict__ xl)
{
    size_t idx = (size_t)blockIdx.x*256 + threadIdx.x;
    int d = (int)(idx & (Dm-1));
    size_t bs = idx >> 10;
    int s = (int)(bs & (Sq-1));
    float v = emb[(size_t)seq[bs]*Dm + d] + pes[(size_t)s*Dm];
    x[idx] = v;
    __nv_bfloat16 h = __float2bfloat16(v);
    xh[idx] = h;
    xl[idx] = __float2bfloat16(v - __bfloat162float(h));
}

// ---------------- softmax ------------------------------------------------------
__global__ void softmax_k(float* __restrict__ S)
{
    float* p = S + (size_t)blockIdx.x*Sq;
    const int t = threadIdx.x;
    __shared__ float red[256];
    float v0 = p[t], v1 = p[t+256];
    red[t] = fmaxf(v0, v1); __syncthreads();
    for (int o = 128; o > 0; o >>= 1) { if (t < o) red[t] = fmaxf(red[t], red[t+o]); __syncthreads(); }
    const float m = red[0]; __syncthreads();
    float e0 = __expf(v0-m), e1 = __expf(v1-m);
    red[t] = e0 + e1; __syncthreads();
    for (int o = 128; o > 0; o >>= 1) { if (t < o) red[t] += red[t+o]; __syncthreads(); }
    const float inv = 1.f/red[0];
    p[t] = e0*inv; p[t+256] = e1*inv;
}

// ---------------- SIMT fp32 GEMM (attention path) ------------------------------
constexpr int BM = 128, BNs = 128, BKt = 8, TM = 8, TN = 8;
enum { EPI_NONE = 0, EPI_RESID_BN = 3 };

template <int EPI, bool TRANSB, bool WB16>
__global__ void __launch_bounds__(256, 2)
gemm_k(const float* __restrict__ A, const float* __restrict__ B,
       const float* __restrict__ bias, float* __restrict__ C,
       int M, int N, int K, int lda, int ldb, int ldc,
       long sA, long sB, long sC, float alpha,
       const float* __restrict__ resid,
       const float* __restrict__ gamma, const float* __restrict__ beta,
       const float* __restrict__ mean,  const float* __restrict__ var,
       __nv_bfloat16* __restrict__ Oh, __nv_bfloat16* __restrict__ Ol)
{
    __shared__ float As[BKt][BM+4];
    __shared__ float Bs[BKt][BNs+4];
    A += (long)blockIdx.z*sA; B += (long)blockIdx.z*sB; C += (long)blockIdx.z*sC;
    const int m0 = blockIdx.y*BM, n0 = blockIdx.x*BNs;
    const int tid = threadIdx.x, tx = tid&15, ty = tid>>4;
    const int arow = tid>>1, acol = (tid&1)<<2;
    const int brow = tid>>5, bcol = (tid&31)<<2;
    const int bn = tid>>1, bkk = (tid&1)<<2;

    float acc[TM][TN];
#pragma unroll
    for (int i=0;i<TM;i++)
#pragma unroll
        for (int j=0;j<TN;j++) acc[i][j]=0.f;

    for (int k0 = 0; k0 < K; k0 += BKt) {
        float4 av = *(const float4*)(A + (long)(m0+arow)*lda + k0 + acol);
        As[acol+0][arow]=av.x; As[acol+1][arow]=av.y; As[acol+2][arow]=av.z; As[acol+3][arow]=av.w;
        if (!TRANSB) {
            float4 bv = make_float4(0,0,0,0);
            if (n0+bcol < N) bv = *(const float4*)(B + (long)(k0+brow)*ldb + n0 + bcol);
            Bs[brow][bcol+0]=bv.x; Bs[brow][bcol+1]=bv.y; Bs[brow][bcol+2]=bv.z; Bs[brow][bcol+3]=bv.w;
        } else {
            float4 bv = make_float4(0,0,0,0);
            if (n0+bn < N) bv = *(const float4*)(B + (long)(n0+bn)*ldb + k0 + bkk);
            Bs[bkk+0][bn]=bv.x; Bs[bkk+1][bn]=bv.y; Bs[bkk+2][bn]=bv.z; Bs[bkk+3][bn]=bv.w;
        }
        __syncthreads();
#pragma unroll
        for (int kk = 0; kk < BKt; kk++) {
            float4 a0 = *(const float4*)(&As[kk][ty*TM]);
            float4 a1 = *(const float4*)(&As[kk][ty*TM+4]);
            float4 b0 = *(const float4*)(&Bs[kk][tx*TN]);
            float4 b1 = *(const float4*)(&Bs[kk][tx*TN+4]);
            float a[TM]={a0.x,a0.y,a0.z,a0.w,a1.x,a1.y,a1.z,a1.w};
            float b[TN]={b0.x,b0.y,b0.z,b0.w,b1.x,b1.y,b1.z,b1.w};
#pragma unroll
            for (int i=0;i<TM;i++)
#pragma unroll
                for (int j=0;j<TN;j++) acc[i][j]=fmaf(a[i],b[j],acc[i][j]);
        }
        __syncthreads();
    }

#pragma unroll
    for (int i = 0; i < TM; i++) {
        const int m = m0 + ty*TM + i;
#pragma unroll
        for (int j = 0; j < TN; j++) {
            const int n = n0 + tx*TN + j;
            if (n < N) {
                float v = acc[i][j]*alpha;
                if (EPI == EPI_RESID_BN) {
                    v += bias[n] + resid[(long)m*ldc + n];
                    v = gamma[n]*(v - mean[n])*rsqrtf(var[n] + 1e-3f) + beta[n];
                }
                C[(long)m*ldc + n] = v;
                if (WB16) {
                    __nv_bfloat16 h = __float2bfloat16(v);
                    Oh[(long)m*ldc + n] = h;
                    Ol[(long)m*ldc + n] = __float2bfloat16(v - __bfloat162float(h));
                }
            }
        }
    }
}

// ---------------- host ----------------------------------------------------------
static const int SM64  = 2*(32768 + 2*64*128);    //  98304
static const int SM128 = 2*(32768 + 2*128*128);   // 131072

extern "C" void kernel_launch(void* const* d_in, const int* in_sizes, int n_in,
                              void* d_out, int out_size)
{
    const int*   seq = (const int*)  d_in[0];
    const float* emb = (const float*)d_in[1];
    const float* pes = (const float*)d_in[2];
    const float* wq  = (const float*)d_in[3];
    const float* bqp = (const float*)d_in[4];
    const float* wk  = (const float*)d_in[5];
    const float* bkp = (const float*)d_in[6];
    const float* wv  = (const float*)d_in[7];
    const float* bvp = (const float*)d_in[8];
    const float* wo  = (const float*)d_in[9];
    const float* bo  = (const float*)d_in[10];
    const float* ag  = (const float*)d_in[11];
    const float* ab  = (const float*)d_in[12];
    const float* am  = (const float*)d_in[13];
    const float* avv = (const float*)d_in[14];
    const float* w1  = (const float*)d_in[15];
    const float* b1  = (const float*)d_in[16];
    const float* w2  = (const float*)d_in[17];
    const float* b2  = (const float*)d_in[18];
    const float* fg  = (const float*)d_in[19];
    const float* fb  = (const float*)d_in[20];
    const float* fm  = (const float*)d_in[21];
    const float* fv  = (const float*)d_in[22];
    float* out = (float*)d_out;

    float *px, *pqkv, *psc, *phd, *pbq;
    __nv_bfloat16 *pxh, *pxl, *phh, *phl, *pwqh, *pwql, *pw1h, *pw1l, *pw2h, *pw2l;
    cudaGetSymbolAddress((void**)&px,   g_x);
    cudaGetSymbolAddress((void**)&pxh,  g_xh);
    cudaGetSymbolAddress((void**)&pxl,  g_xl);
    cudaGetSymbolAddress((void**)&pqkv, g_qkv);
    cudaGetSymbolAddress((void**)&psc,  g_sc);
    cudaGetSymbolAddress((void**)&phd,  g_hd);
    cudaGetSymbolAddress((void**)&phh,  g_hh);
    cudaGetSymbolAddress((void**)&phl,  g_hl);
    cudaGetSymbolAddress((void**)&pwqh, g_wqh);
    cudaGetSymbolAddress((void**)&pwql, g_wql);
    cudaGetSymbolAddress((void**)&pw1h, g_w1h);
    cudaGetSymbolAddress((void**)&pw1l, g_w1l);
    cudaGetSymbolAddress((void**)&pw2h, g_w2h);
    cudaGetSymbolAddress((void**)&pw2l, g_w2l);
    cudaGetSymbolAddress((void**)&pbq,  g_bqkv);

    cudaFuncSetAttribute(mma_gemm<64,  TCE_BIAS, false>, cudaFuncAttributeMaxDynamicSharedMemorySize, SM64);
    cudaFuncSetAttribute(mma_gemm<128, TCE_RELU, true >, cudaFuncAttributeMaxDynamicSharedMemorySize, SM128);
    cudaFuncSetAttribute(mma_gemm<128, TCE_BN,   true >, cudaFuncAttributeMaxDynamicSharedMemorySize, SM128);
    cudaFuncSetAttribute(mma_gemm<128, TCE_BN,   false>, cudaFuncAttributeMaxDynamicSharedMemorySize, SM128);

    // ---- weight prep (in-graph, every replay) ----
    dim3 tb(32, 8);
    for (int l = 0; l < NL; l++) {
        wsplit<<<dim3(Dm/32, 2),   tb>>>(wq + (size_t)l*Dm*DKh, Dm, DKh,
                                         pwqh + (size_t)l*192*Dm,          pwql + (size_t)l*192*Dm);
        wsplit<<<dim3(Dm/32, 2),   tb>>>(wk + (size_t)l*Dm*DKh, Dm, DKh,
                                         pwqh + (size_t)l*192*Dm + 64*Dm,  pwql + (size_t)l*192*Dm + 64*Dm);
        wsplit<<<dim3(Dm/32, 2),   tb>>>(wv + (size_t)l*Dm*DKh, Dm, DKh,
                                         pwqh + (size_t)l*192*Dm + 128*Dm, pwql + (size_t)l*192*Dm + 128*Dm);
        wsplit<<<dim3(Dm/32, FFd/32), tb>>>(w1 + (size_t)l*Dm*FFd, Dm, FFd,
                                            pw1h + (size_t)l*FFd*Dm, pw1l + (size_t)l*FFd*Dm);
        wsplit<<<dim3(FFd/32, Dm/32), tb>>>(w2 + (size_t)l*FFd*Dm, FFd, Dm,
                                            pw2h + (size_t)l*Dm*FFd, pw2l + (size_t)l*Dm*FFd);
    }
    biaspack<<<3, 256>>>(bqp, bkp, bvp, pbq);

    embed_k<<<(Mrows*Dm)/256, 256>>>(seq, emb, pes, px, pxh, pxl);

    for (int l = 0; l < NL; l++) {
        // QKV fused: [4096,192] = x @ Wqkv^T + b
        mma_gemm<64, TCE_BIAS, false><<<dim3(3, 32), 256, SM64>>>(
            pxh, pxl, pwqh + (size_t)l*192*Dm, pwql + (size_t)l*192*Dm,
            pbq + l*192, Dm, pqkv, 192, nullptr, nullptr,
            nullptr, nullptr, nullptr, nullptr, nullptr);

        // scores = Q @ K^T / 8  (batched over B)
        gemm_k<EPI_NONE, true, false><<<dim3(4, 4, Bq), 256>>>(
            pqkv, pqkv + 64, nullptr, psc, Sq, Sq, DKh, 192, 192, Sq,
            (long)Sq*192, (long)Sq*192, (long)Sq*Sq, 0.125f,
            nullptr, nullptr, nullptr, nullptr, nullptr, nullptr, nullptr);

        softmax_k<<<Mrows, 256>>>(psc);

        // head = P @ V (batched)
        gemm_k<EPI_NONE, false, false><<<dim3(1, 4, Bq), 256>>>(
            psc, pqkv + 128, nullptr, phd, Sq, DKh, Sq, Sq, 192, DKh,
            (long)Sq*Sq, (long)Sq*192, (long)Sq*DKh, 1.f,
            nullptr, nullptr, nullptr, nullptr, nullptr, nullptr, nullptr);

        // x = BN(x + head @ wo + bo), also emit bf16 splits of x
        gemm_k<EPI_RESID_BN, false, true><<<dim3(8, 32), 256>>>(
            phd, wo + (size_t)l*DKh*Dm, bo + l*Dm, px, Mrows, Dm, DKh, DKh, Dm, Dm,
            0, 0, 0, 1.f, px, ag + l*Dm, ab + l*Dm, am + l*Dm, avv + l*Dm, pxh, pxl);

        // h = relu(x @ w1 + b1) -> bf16 splits only
        mma_gemm<128, TCE_RELU, true><<<dim3(FFd/128, 32), 256, SM128>>>(
            pxh, pxl, pw1h + (size_t)l*FFd*Dm, pw1l + (size_t)l*FFd*Dm,
            b1 + l*FFd, Dm, nullptr, FFd, phh, phl,
            nullptr, nullptr, nullptr, nullptr, nullptr);

        // x = BN(x + h @ w2 + b2)
        if (l < NL-1) {
            mma_gemm<128, TCE_BN, true><<<dim3(Dm/128, 32), 256, SM128>>>(
                phh, phl, pw2h + (size_t)l*Dm*FFd, pw2l + (size_t)l*Dm*FFd,
                b2 + l*Dm, FFd, px, Dm, pxh, pxl,
                px, fg + l*Dm, fb + l*Dm, fm + l*Dm, fv + l*Dm);
        } else {
            mma_gemm<128, TCE_BN, false><<<dim3(Dm/128, 32), 256, SM128>>>(
                phh, phl, pw2h + (size_t)l*Dm*FFd, pw2l + (size_t)l*Dm*FFd,
                b2 + l*Dm, FFd, out, Dm, nullptr, nullptr,
                px, fg + l*Dm, fb + l*Dm, fm + l*Dm, fv + l*Dm);
        }
    }
}